// round 1
// baseline (speedup 1.0000x reference)
#include <cuda_runtime.h>
#include <math.h>

#define BSZ 16
#define SEQ 512
#define DM 1024
#define NH 16
#define HDIM 64
#define DFF 4096
#define MROWS (BSZ * SEQ)  // 8192
#define QKVD (3 * DM)      // 3072

// ---------------- scratch (device globals; no cudaMalloc allowed) ----------
__device__ float g_xn[(size_t)MROWS * DM];      // 33.5 MB (LN output, reused)
__device__ float g_qkv[(size_t)MROWS * QKVD];   // 100 MB
__device__ float g_attn[(size_t)MROWS * DM];    // 33.5 MB
__device__ float g_ffn[(size_t)MROWS * DFF];    // 134 MB

// ---------------- LayerNorm: one block (256 thr) per row of 1024 ----------
__global__ void ln_kernel(const float* __restrict__ x, const float* __restrict__ w,
                          const float* __restrict__ b, float* __restrict__ out) {
    int row = blockIdx.x;
    int tid = threadIdx.x;
    const float4* xr = (const float4*)(x + (size_t)row * DM);
    float4 v = xr[tid];
    float s = v.x + v.y + v.z + v.w;
    float s2 = v.x * v.x + v.y * v.y + v.z * v.z + v.w * v.w;
    __shared__ float red[16];
#pragma unroll
    for (int off = 16; off > 0; off >>= 1) {
        s += __shfl_xor_sync(0xffffffffu, s, off);
        s2 += __shfl_xor_sync(0xffffffffu, s2, off);
    }
    int wid = tid >> 5;
    if ((tid & 31) == 0) { red[wid] = s; red[8 + wid] = s2; }
    __syncthreads();
    if (tid < 32) {
        s = (tid < 8) ? red[tid] : 0.f;
        s2 = (tid < 8) ? red[8 + tid] : 0.f;
#pragma unroll
        for (int off = 4; off > 0; off >>= 1) {
            s += __shfl_xor_sync(0xffffffffu, s, off);
            s2 += __shfl_xor_sync(0xffffffffu, s2, off);
        }
        if (tid == 0) {
            float mu = s * (1.f / DM);
            float var = s2 * (1.f / DM) - mu * mu;
            red[0] = mu;
            red[1] = rsqrtf(var + 1e-5f);
        }
    }
    __syncthreads();
    float mu = red[0], rstd = red[1];
    float4 wv = ((const float4*)w)[tid];
    float4 bv = ((const float4*)b)[tid];
    float4 o;
    o.x = (v.x - mu) * rstd * wv.x + bv.x;
    o.y = (v.y - mu) * rstd * wv.y + bv.y;
    o.z = (v.z - mu) * rstd * wv.z + bv.z;
    o.w = (v.w - mu) * rstd * wv.w + bv.w;
    ((float4*)(out + (size_t)row * DM))[tid] = o;
}

// ---------------- SGEMM: C[M,N] = A[M,K] * W[N,K]^T + bias (+ epilogue) ----
// EPI: 0 = bias only, 1 = gelu(bias+acc), 2 = res + bias + acc
// 128x128 block tile, BK=8, 256 threads, 8x8 per thread (2x2 of 4x4 frags)
template <int EPI>
__global__ __launch_bounds__(256, 2) void sgemm_kernel(
    const float* __restrict__ A, const float* __restrict__ W,
    const float* __restrict__ bias, const float* __restrict__ res,
    float* __restrict__ C, int M, int N, int K) {
    __shared__ float As[8][128];
    __shared__ float Bs[8][128];
    int tid = threadIdx.x;
    int tx = tid & 15, ty = tid >> 4;
    int bm = blockIdx.y, bn = blockIdx.x;
    int arow = tid >> 1;
    int kc = (tid & 1) << 2;
    const float* Ab = A + (size_t)(bm * 128 + arow) * K + kc;
    const float* Wb = W + (size_t)(bn * 128 + arow) * K + kc;

    float acc[8][8];
#pragma unroll
    for (int i = 0; i < 8; i++)
#pragma unroll
        for (int j = 0; j < 8; j++) acc[i][j] = 0.f;

    for (int k0 = 0; k0 < K; k0 += 8) {
        float4 av = *(const float4*)(Ab + k0);
        float4 wv = *(const float4*)(Wb + k0);
        As[kc + 0][arow] = av.x;
        As[kc + 1][arow] = av.y;
        As[kc + 2][arow] = av.z;
        As[kc + 3][arow] = av.w;
        Bs[kc + 0][arow] = wv.x;
        Bs[kc + 1][arow] = wv.y;
        Bs[kc + 2][arow] = wv.z;
        Bs[kc + 3][arow] = wv.w;
        __syncthreads();
#pragma unroll
        for (int kk = 0; kk < 8; kk++) {
            float4 a0 = *(const float4*)&As[kk][ty * 4];
            float4 a1 = *(const float4*)&As[kk][64 + ty * 4];
            float4 b0 = *(const float4*)&Bs[kk][tx * 4];
            float4 b1 = *(const float4*)&Bs[kk][64 + tx * 4];
            float a[8] = {a0.x, a0.y, a0.z, a0.w, a1.x, a1.y, a1.z, a1.w};
            float bb[8] = {b0.x, b0.y, b0.z, b0.w, b1.x, b1.y, b1.z, b1.w};
#pragma unroll
            for (int i = 0; i < 8; i++)
#pragma unroll
                for (int j = 0; j < 8; j++) acc[i][j] += a[i] * bb[j];
        }
        __syncthreads();
    }

#pragma unroll
    for (int i = 0; i < 8; i++) {
        int row = bm * 128 + ((i >> 2) << 6) + ty * 4 + (i & 3);
#pragma unroll
        for (int jh = 0; jh < 2; jh++) {
            int col = bn * 128 + (jh << 6) + tx * 4;
            float4 bv = *(const float4*)(bias + col);
            float bvv[4] = {bv.x, bv.y, bv.z, bv.w};
            float v[4];
#pragma unroll
            for (int u = 0; u < 4; u++) v[u] = acc[i][jh * 4 + u] + bvv[u];
            if (EPI == 1) {
#pragma unroll
                for (int u = 0; u < 4; u++)
                    v[u] = 0.5f * v[u] * (1.f + erff(v[u] * 0.70710678118654752f));
            } else if (EPI == 2) {
                float4 rv = *(const float4*)(res + (size_t)row * N + col);
                v[0] += rv.x; v[1] += rv.y; v[2] += rv.z; v[3] += rv.w;
            }
            float4 o = make_float4(v[0], v[1], v[2], v[3]);
            *(float4*)(C + (size_t)row * N + col) = o;
        }
    }
}

// ---------------- Flash-style attention -----------------------------------
// grid: (q_tiles=8, h=16, b=16); block = 256 threads
// Per block: 64 q-rows x full 512 keys, hd=64, online softmax with rel bias.
__global__ __launch_bounds__(256, 4) void attn_kernel(
    const float* __restrict__ qkv, const float* __restrict__ rel_bias,
    float* __restrict__ attn_out) {
    __shared__ float Qt[64 * 64];   // Qt[d*64 + r]  (transposed)
    __shared__ float KVs[64 * 64];  // K transposed, then V natural
    __shared__ float Ps[64 * 64];   // P[i*64 + j]
    int tid = threadIdx.x;
    int tx = tid & 15, ty = tid >> 4;
    int qt = blockIdx.x, h = blockIdx.y, b = blockIdx.z;

    const float* qbase = qkv + (size_t)(b * SEQ + qt * 64) * QKVD + h * HDIM;
    const float* kbase = qkv + (size_t)(b * SEQ) * QKVD + DM + h * HDIM;
    const float* vbase = kbase + DM;
    const float* biasrow = rel_bias + h * (2 * SEQ - 1);

    // load Q tile transposed
    {
        int r = tid >> 2;
        int d0 = (tid & 3) << 4;
        const float* src = qbase + (size_t)r * QKVD + d0;
#pragma unroll
        for (int u = 0; u < 16; u += 4) {
            float4 v = *(const float4*)(src + u);
            Qt[(d0 + u + 0) * 64 + r] = v.x;
            Qt[(d0 + u + 1) * 64 + r] = v.y;
            Qt[(d0 + u + 2) * 64 + r] = v.z;
            Qt[(d0 + u + 3) * 64 + r] = v.w;
        }
    }

    float m[4], l[4], o[4][4];
#pragma unroll
    for (int i = 0; i < 4; i++) {
        m[i] = -1e30f;
        l[i] = 0.f;
#pragma unroll
        for (int c = 0; c < 4; c++) o[i][c] = 0.f;
    }

    for (int kt = 0; kt < 8; kt++) {
        __syncthreads();  // prev iter's V reads done (also covers Qt store, iter 0)
        // load K tile transposed
        {
            int r = tid >> 2;
            int d0 = (tid & 3) << 4;
            const float* src = kbase + (size_t)(kt * 64 + r) * QKVD + d0;
#pragma unroll
            for (int u = 0; u < 16; u += 4) {
                float4 v = *(const float4*)(src + u);
                KVs[(d0 + u + 0) * 64 + r] = v.x;
                KVs[(d0 + u + 1) * 64 + r] = v.y;
                KVs[(d0 + u + 2) * 64 + r] = v.z;
                KVs[(d0 + u + 3) * 64 + r] = v.w;
            }
        }
        __syncthreads();

        // S = Q K^T (4x4 per thread over 64x64 tile)
        float s[4][4];
#pragma unroll
        for (int i = 0; i < 4; i++)
#pragma unroll
            for (int j = 0; j < 4; j++) s[i][j] = 0.f;
#pragma unroll 16
        for (int d = 0; d < 64; d++) {
            float4 a = *(const float4*)&Qt[d * 64 + ty * 4];
            float4 bq = *(const float4*)&KVs[d * 64 + tx * 4];
            float aa[4] = {a.x, a.y, a.z, a.w};
            float bb[4] = {bq.x, bq.y, bq.z, bq.w};
#pragma unroll
            for (int i = 0; i < 4; i++)
#pragma unroll
                for (int j = 0; j < 4; j++) s[i][j] += aa[i] * bb[j];
        }

        // scale + rel-pos bias (no clipping needed: S == MAX_LEN)
        int qg = qt * 64 + ty * 4;
        int kg = kt * 64 + tx * 4;
#pragma unroll
        for (int i = 0; i < 4; i++)
#pragma unroll
            for (int j = 0; j < 4; j++)
                s[i][j] = s[i][j] * 0.125f +
                          __ldg(&biasrow[(qg + i) - (kg + j) + (SEQ - 1)]);

        // row max across the 16-lane tx group
        float mt[4];
#pragma unroll
        for (int i = 0; i < 4; i++) {
            mt[i] = fmaxf(fmaxf(s[i][0], s[i][1]), fmaxf(s[i][2], s[i][3]));
#pragma unroll
            for (int off = 8; off > 0; off >>= 1)
                mt[i] = fmaxf(mt[i], __shfl_xor_sync(0xffffffffu, mt[i], off, 16));
        }
        float fac[4];
#pragma unroll
        for (int i = 0; i < 4; i++) {
            float mn = fmaxf(m[i], mt[i]);
            fac[i] = __expf(m[i] - mn);
            m[i] = mn;
        }
        // p = exp(s - m), row sums
        float rs[4];
#pragma unroll
        for (int i = 0; i < 4; i++) {
            rs[i] = 0.f;
#pragma unroll
            for (int j = 0; j < 4; j++) {
                float p = __expf(s[i][j] - m[i]);
                s[i][j] = p;
                rs[i] += p;
            }
#pragma unroll
            for (int off = 8; off > 0; off >>= 1)
                rs[i] += __shfl_xor_sync(0xffffffffu, rs[i], off, 16);
            l[i] = l[i] * fac[i] + rs[i];
#pragma unroll
            for (int c = 0; c < 4; c++) o[i][c] *= fac[i];
        }
        // store P (natural layout)
#pragma unroll
        for (int i = 0; i < 4; i++)
            *(float4*)&Ps[(ty * 4 + i) * 64 + tx * 4] =
                make_float4(s[i][0], s[i][1], s[i][2], s[i][3]);
        __syncthreads();  // all S-compute reads of K done; P visible

        // load V tile (natural layout) into KVs
        {
            int r = tid >> 2;
            int d0 = (tid & 3) << 4;
            const float* src = vbase + (size_t)(kt * 64 + r) * QKVD + d0;
#pragma unroll
            for (int u = 0; u < 16; u += 4)
                *(float4*)&KVs[r * 64 + d0 + u] = *(const float4*)(src + u);
        }
        __syncthreads();

        // O += P * V
#pragma unroll 16
        for (int j = 0; j < 64; j++) {
            float pa[4];
#pragma unroll
            for (int i = 0; i < 4; i++) pa[i] = Ps[(ty * 4 + i) * 64 + j];
            float4 vb = *(const float4*)&KVs[j * 64 + tx * 4];
            float vv[4] = {vb.x, vb.y, vb.z, vb.w};
#pragma unroll
            for (int i = 0; i < 4; i++)
#pragma unroll
                for (int c = 0; c < 4; c++) o[i][c] += pa[i] * vv[c];
        }
    }

    // write out: attn_out[(b*S + q) * DM + h*64 + col]
    float* obase = attn_out + (size_t)(b * SEQ + qt * 64) * DM + h * HDIM;
#pragma unroll
    for (int i = 0; i < 4; i++) {
        float inv = 1.f / l[i];
        float4 r = make_float4(o[i][0] * inv, o[i][1] * inv, o[i][2] * inv,
                               o[i][3] * inv);
        *(float4*)&obase[(size_t)(ty * 4 + i) * DM + tx * 4] = r;
    }
}

// ---------------- launch ---------------------------------------------------
extern "C" void kernel_launch(void* const* d_in, const int* in_sizes, int n_in,
                              void* d_out, int out_size) {
    const float* x = (const float*)d_in[0];
    const float* in_w = (const float*)d_in[1];
    const float* in_b = (const float*)d_in[2];
    const float* out_w = (const float*)d_in[3];
    const float* out_b = (const float*)d_in[4];
    const float* rel_bias = (const float*)d_in[5];
    const float* w1 = (const float*)d_in[6];
    const float* b1 = (const float*)d_in[7];
    const float* w2 = (const float*)d_in[8];
    const float* b2 = (const float*)d_in[9];
    const float* ln1w = (const float*)d_in[10];
    const float* ln1b = (const float*)d_in[11];
    const float* ln2w = (const float*)d_in[12];
    const float* ln2b = (const float*)d_in[13];
    float* out = (float*)d_out;

    float *xn, *qkv, *attn, *ffn;
    cudaGetSymbolAddress((void**)&xn, g_xn);
    cudaGetSymbolAddress((void**)&qkv, g_qkv);
    cudaGetSymbolAddress((void**)&attn, g_attn);
    cudaGetSymbolAddress((void**)&ffn, g_ffn);

    // 1. xn = LN1(x)
    ln_kernel<<<MROWS, 256>>>(x, ln1w, ln1b, xn);
    // 2. qkv = xn @ in_proj_w^T + in_proj_b
    sgemm_kernel<0><<<dim3(QKVD / 128, MROWS / 128), 256>>>(
        xn, in_w, in_b, nullptr, qkv, MROWS, QKVD, DM);
    // 3. attention with rel-pos bias
    attn_kernel<<<dim3(SEQ / 64, NH, BSZ), 256>>>(qkv, rel_bias, attn);
    // 4. out = x + attn @ out_w^T + out_b
    sgemm_kernel<2><<<dim3(DM / 128, MROWS / 128), 256>>>(
        attn, out_w, out_b, x, out, MROWS, DM, DM);
    // 5. xn = LN2(out)
    ln_kernel<<<MROWS, 256>>>(out, ln2w, ln2b, xn);
    // 6. ffn = gelu(xn @ w1^T + b1)
    sgemm_kernel<1><<<dim3(DFF / 128, MROWS / 128), 256>>>(
        xn, w1, b1, nullptr, ffn, MROWS, DFF, DM);
    // 7. out = out + ffn @ w2^T + b2   (in-place residual)
    sgemm_kernel<2><<<dim3(DM / 128, MROWS / 128), 256>>>(
        ffn, w2, b2, out, out, MROWS, DM, DFF);
}

// round 6
// speedup vs baseline: 2.0140x; 2.0140x over previous
#include <cuda_runtime.h>
#include <cuda_bf16.h>
#include <math.h>
#include <stdint.h>

#define BSZ 16
#define SEQ 512
#define DM 1024
#define NH 16
#define HDIM 64
#define DFF 4096
#define MROWS (BSZ * SEQ)  // 8192
#define QKVD (3 * DM)      // 3072

// ---------------- scratch (device globals; no cudaMalloc allowed) ----------
__device__ __align__(16) __nv_bfloat16 g_wh[12582912];            // weights hi
__device__ __align__(16) __nv_bfloat16 g_wl[12582912];            // weights lo
__device__ __align__(16) __nv_bfloat16 g_xh[(size_t)MROWS * DM];  // act pair
__device__ __align__(16) __nv_bfloat16 g_xl[(size_t)MROWS * DM];
__device__ __align__(16) __nv_bfloat16 g_ah[(size_t)MROWS * DFF]; // ffn pair
__device__ __align__(16) __nv_bfloat16 g_al[(size_t)MROWS * DFF];
__device__ float g_qkv[(size_t)MROWS * QKVD];
__device__ float g_attn[(size_t)MROWS * DM];

// ---------------- PTX helpers ----------------------------------------------
__device__ __forceinline__ uint32_t s2u(const void* p) {
    uint32_t a;
    asm("{ .reg .u64 t; cvta.to.shared.u64 t, %1; cvt.u32.u64 %0, t; }"
        : "=r"(a) : "l"(p));
    return a;
}
__device__ __forceinline__ void cp_async16(uint32_t dst, const void* src) {
    asm volatile("cp.async.cg.shared.global [%0], [%1], 16;"
                 :: "r"(dst), "l"(src) : "memory");
}
__device__ __forceinline__ void cp_commit() {
    asm volatile("cp.async.commit_group;" ::: "memory");
}
template <int N>
__device__ __forceinline__ void cp_wait() {
    asm volatile("cp.async.wait_group %0;" :: "n"(N) : "memory");
}
#define LDSM4(d, a) \
    asm volatile("ldmatrix.sync.aligned.m8n8.x4.shared.b16 {%0,%1,%2,%3}, [%4];" \
                 : "=r"((d)[0]), "=r"((d)[1]), "=r"((d)[2]), "=r"((d)[3]) : "r"(a))
#define MMA16816(c, a, b) \
    asm volatile( \
        "mma.sync.aligned.m16n8k16.row.col.f32.bf16.bf16.f32 " \
        "{%0,%1,%2,%3},{%4,%5,%6,%7},{%8,%9},{%0,%1,%2,%3};" \
        : "+f"((c)[0]), "+f"((c)[1]), "+f"((c)[2]), "+f"((c)[3]) \
        : "r"((a)[0]), "r"((a)[1]), "r"((a)[2]), "r"((a)[3]), \
          "r"((b)[0]), "r"((b)[1]))

// SMEM tile geometry: 128 rows x 32 bf16 data, 80-byte row stride (pad 8)
#define ROWB 80
#define TILEB (128 * ROWB)      // 10240
#define STAGEB (4 * TILEB)      // 40960
#define SMEM_BYTES (2 * STAGEB) // 81920

__device__ __forceinline__ float gelu_f(float v) {
    return 0.5f * v * (1.f + erff(v * 0.70710678118654752f));
}

// ---------------- convert fp32 -> bf16 hi/lo pair --------------------------
__global__ void cvt_pair(const float* __restrict__ in, __nv_bfloat16* __restrict__ oh,
                         __nv_bfloat16* __restrict__ ol, int n4) {
    int i = blockIdx.x * blockDim.x + threadIdx.x;
    if (i >= n4) return;
    float4 v = ((const float4*)in)[i];
    __nv_bfloat16 hx = __float2bfloat16(v.x), hy = __float2bfloat16(v.y);
    __nv_bfloat16 hz = __float2bfloat16(v.z), hw = __float2bfloat16(v.w);
    __nv_bfloat162 h0, h1, l0, l1;
    h0.x = hx; h0.y = hy; h1.x = hz; h1.y = hw;
    l0.x = __float2bfloat16(v.x - __bfloat162float(hx));
    l0.y = __float2bfloat16(v.y - __bfloat162float(hy));
    l1.x = __float2bfloat16(v.z - __bfloat162float(hz));
    l1.y = __float2bfloat16(v.w - __bfloat162float(hw));
    ((__nv_bfloat162*)oh)[i * 2] = h0;
    ((__nv_bfloat162*)oh)[i * 2 + 1] = h1;
    ((__nv_bfloat162*)ol)[i * 2] = l0;
    ((__nv_bfloat162*)ol)[i * 2 + 1] = l1;
}

// ---------------- LayerNorm -> bf16 hi/lo pair -----------------------------
__global__ void ln_pair_kernel(const float* __restrict__ x, const float* __restrict__ w,
                               const float* __restrict__ b, __nv_bfloat16* __restrict__ oh,
                               __nv_bfloat16* __restrict__ ol) {
    int row = blockIdx.x;
    int tid = threadIdx.x;
    const float4* xr = (const float4*)(x + (size_t)row * DM);
    float4 v = xr[tid];
    float s = v.x + v.y + v.z + v.w;
    float s2 = v.x * v.x + v.y * v.y + v.z * v.z + v.w * v.w;
    __shared__ float red[16];
#pragma unroll
    for (int off = 16; off > 0; off >>= 1) {
        s += __shfl_xor_sync(0xffffffffu, s, off);
        s2 += __shfl_xor_sync(0xffffffffu, s2, off);
    }
    int wid = tid >> 5;
    if ((tid & 31) == 0) { red[wid] = s; red[8 + wid] = s2; }
    __syncthreads();
    if (tid < 32) {
        s = (tid < 8) ? red[tid] : 0.f;
        s2 = (tid < 8) ? red[8 + tid] : 0.f;
#pragma unroll
        for (int off = 4; off > 0; off >>= 1) {
            s += __shfl_xor_sync(0xffffffffu, s, off);
            s2 += __shfl_xor_sync(0xffffffffu, s2, off);
        }
        if (tid == 0) {
            float mu = s * (1.f / DM);
            float var = s2 * (1.f / DM) - mu * mu;
            red[0] = mu;
            red[1] = rsqrtf(var + 1e-5f);
        }
    }
    __syncthreads();
    float mu = red[0], rstd = red[1];
    float4 wv = ((const float4*)w)[tid];
    float4 bv = ((const float4*)b)[tid];
    float4 o;
    o.x = (v.x - mu) * rstd * wv.x + bv.x;
    o.y = (v.y - mu) * rstd * wv.y + bv.y;
    o.z = (v.z - mu) * rstd * wv.z + bv.z;
    o.w = (v.w - mu) * rstd * wv.w + bv.w;
    __nv_bfloat16 hx = __float2bfloat16(o.x), hy = __float2bfloat16(o.y);
    __nv_bfloat16 hz = __float2bfloat16(o.z), hw = __float2bfloat16(o.w);
    __nv_bfloat162 h0, h1, l0, l1;
    h0.x = hx; h0.y = hy; h1.x = hz; h1.y = hw;
    l0.x = __float2bfloat16(o.x - __bfloat162float(hx));
    l0.y = __float2bfloat16(o.y - __bfloat162float(hy));
    l1.x = __float2bfloat16(o.z - __bfloat162float(hz));
    l1.y = __float2bfloat16(o.w - __bfloat162float(hw));
    size_t base = (size_t)row * DM;
    ((__nv_bfloat162*)(oh + base))[tid * 2] = h0;
    ((__nv_bfloat162*)(oh + base))[tid * 2 + 1] = h1;
    ((__nv_bfloat162*)(ol + base))[tid * 2] = l0;
    ((__nv_bfloat162*)(ol + base))[tid * 2 + 1] = l1;
}

// ---------------- bf16x3 GEMM via mma.sync (HMMA) --------------------------
// C[M,N] = A*W^T (+bias, EPI). A=Ah+Al, W=Wh+Wl (K-major).
// 128x128 CTA tile, BK=32, 256 thr, warp tile 32x64, cp.async double buffer.
// EPI: 0 = bias -> Cf; 1 = gelu(bias+acc) -> (Oh,Ol); 2 = res+bias+acc -> Cf
template <int EPI>
__global__ void __launch_bounds__(256, 1) gemm_bf16x3(
    const __nv_bfloat16* __restrict__ Ah, const __nv_bfloat16* __restrict__ Al,
    const __nv_bfloat16* __restrict__ Wh, const __nv_bfloat16* __restrict__ Wl,
    const float* __restrict__ bias, const float* __restrict__ res,
    float* __restrict__ Cf, __nv_bfloat16* __restrict__ Oh,
    __nv_bfloat16* __restrict__ Ol, int N, int K) {
    extern __shared__ char smem[];
    uint32_t sbase = s2u(smem);
    int tid = threadIdx.x;
    int w = tid >> 5, lane = tid & 31;
    int bm = blockIdx.y, bn = blockIdx.x;
    int mbase = (w & 3) * 32, nbase = (w >> 2) * 64;

    const __nv_bfloat16* tsrc[4];
    tsrc[0] = Ah + (size_t)bm * 128 * K;
    tsrc[1] = Al + (size_t)bm * 128 * K;
    tsrc[2] = Wh + (size_t)bn * 128 * K;
    tsrc[3] = Wl + (size_t)bn * 128 * K;

    // per-thread load coords (2 chunks of 16B per tile per stage)
    int r0 = tid >> 2, c0 = tid & 3;              // idx = tid
    int r1 = (tid + 256) >> 2, c1 = tid & 3;      // idx = tid + 256

    // ldmatrix per-lane offsets
    int g = lane >> 3, lr = lane & 7;
    // A: matrices (m0-7,k0-7),(m8-15,k0-7),(m0-7,k8-15),(m8-15,k8-15)
    uint32_t offA = (uint32_t)((mbase + (g & 1) * 8 + lr) * ROWB + (g >> 1) * 16);
    // B: (n0-7,k0-7),(n0-7,k8-15),(n8-15,k0-7),(n8-15,k8-15)
    uint32_t offB = (uint32_t)((nbase + (g >> 1) * 8 + lr) * ROWB + (g & 1) * 16);

    float acc[2][8][4];
#pragma unroll
    for (int mt = 0; mt < 2; mt++)
#pragma unroll
        for (int nt = 0; nt < 8; nt++)
#pragma unroll
            for (int u = 0; u < 4; u++) acc[mt][nt][u] = 0.f;

    int NK = K >> 5;  // BK = 32

    // prologue: stage 0
    {
        uint32_t sb = sbase;
#pragma unroll
        for (int t = 0; t < 4; t++) {
            cp_async16(sb + t * TILEB + r0 * ROWB + c0 * 16,
                       tsrc[t] + (size_t)r0 * K + c0 * 8);
            cp_async16(sb + t * TILEB + r1 * ROWB + c1 * 16,
                       tsrc[t] + (size_t)r1 * K + c1 * 8);
        }
        cp_commit();
    }

    for (int k = 0; k < NK; k++) {
        if (k + 1 < NK) {
            uint32_t sb = sbase + ((k + 1) & 1) * STAGEB;
            int k0 = (k + 1) << 5;
#pragma unroll
            for (int t = 0; t < 4; t++) {
                cp_async16(sb + t * TILEB + r0 * ROWB + c0 * 16,
                           tsrc[t] + (size_t)r0 * K + k0 + c0 * 8);
                cp_async16(sb + t * TILEB + r1 * ROWB + c1 * 16,
                           tsrc[t] + (size_t)r1 * K + k0 + c1 * 8);
            }
            cp_commit();
            cp_wait<1>();
        } else {
            cp_wait<0>();
        }
        __syncthreads();

        uint32_t sb = sbase + (k & 1) * STAGEB;
        uint32_t aAh = sb + offA, aAl = sb + TILEB + offA;
        uint32_t aBh = sb + 2 * TILEB + offB, aBl = sb + 3 * TILEB + offB;

#pragma unroll
        for (int ks = 0; ks < 2; ks++) {
            uint32_t ko = ks * 32;  // bytes: k16 step = 2 chunks = 32B
            uint32_t ah[2][4], al[2][4];
            LDSM4(ah[0], aAh + ko);
            LDSM4(ah[1], aAh + ko + 16 * ROWB);
            LDSM4(al[0], aAl + ko);
            LDSM4(al[1], aAl + ko + 16 * ROWB);
            uint32_t bh[8][2], bl[8][2];
#pragma unroll
            for (int p = 0; p < 4; p++) {
                uint32_t q[4];
                LDSM4(q, aBh + ko + p * (16 * ROWB));
                bh[2 * p][0] = q[0]; bh[2 * p][1] = q[1];
                bh[2 * p + 1][0] = q[2]; bh[2 * p + 1][1] = q[3];
                LDSM4(q, aBl + ko + p * (16 * ROWB));
                bl[2 * p][0] = q[0]; bl[2 * p][1] = q[1];
                bl[2 * p + 1][0] = q[2]; bl[2 * p + 1][1] = q[3];
            }
#pragma unroll
            for (int mt = 0; mt < 2; mt++)
#pragma unroll
                for (int nt = 0; nt < 8; nt++) {
                    MMA16816(acc[mt][nt], ah[mt], bh[nt]);
                    MMA16816(acc[mt][nt], ah[mt], bl[nt]);
                    MMA16816(acc[mt][nt], al[mt], bh[nt]);
                }
        }
        __syncthreads();
    }

    // ---------------- epilogue (registers only) ----------------
    int l4 = lane >> 2, l2 = (lane & 3) * 2;
#pragma unroll
    for (int mt = 0; mt < 2; mt++) {
        int row = bm * 128 + mbase + mt * 16 + l4;
#pragma unroll
        for (int nt = 0; nt < 8; nt++) {
            int col = bn * 128 + nbase + nt * 8 + l2;
            float2 bv = *(const float2*)(bias + col);
            float v0 = acc[mt][nt][0] + bv.x;
            float v1 = acc[mt][nt][1] + bv.y;
            float v2 = acc[mt][nt][2] + bv.x;
            float v3 = acc[mt][nt][3] + bv.y;
            size_t p0 = (size_t)row * N + col;
            size_t p1 = (size_t)(row + 8) * N + col;
            if (EPI == 2) {
                float2 rv0 = *(const float2*)(res + p0);
                float2 rv1 = *(const float2*)(res + p1);
                v0 += rv0.x; v1 += rv0.y; v2 += rv1.x; v3 += rv1.y;
            }
            if (EPI == 1) {
                v0 = gelu_f(v0); v1 = gelu_f(v1);
                v2 = gelu_f(v2); v3 = gelu_f(v3);
                __nv_bfloat16 h0 = __float2bfloat16(v0), h1 = __float2bfloat16(v1);
                __nv_bfloat16 h2 = __float2bfloat16(v2), h3 = __float2bfloat16(v3);
                __nv_bfloat162 hp0, hp1, lp0, lp1;
                hp0.x = h0; hp0.y = h1; hp1.x = h2; hp1.y = h3;
                lp0.x = __float2bfloat16(v0 - __bfloat162float(h0));
                lp0.y = __float2bfloat16(v1 - __bfloat162float(h1));
                lp1.x = __float2bfloat16(v2 - __bfloat162float(h2));
                lp1.y = __float2bfloat16(v3 - __bfloat162float(h3));
                *(__nv_bfloat162*)(Oh + p0) = hp0;
                *(__nv_bfloat162*)(Oh + p1) = hp1;
                *(__nv_bfloat162*)(Ol + p0) = lp0;
                *(__nv_bfloat162*)(Ol + p1) = lp1;
            } else {
                *(float2*)(Cf + p0) = make_float2(v0, v1);
                *(float2*)(Cf + p1) = make_float2(v2, v3);
            }
        }
    }
}

// ---------------- Flash-style attention (fp32) ------------------------------
__global__ __launch_bounds__(256, 4) void attn_kernel(
    const float* __restrict__ qkv, const float* __restrict__ rel_bias,
    float* __restrict__ attn_out) {
    __shared__ float Qt[64 * 64];
    __shared__ float KVs[64 * 64];
    __shared__ float Ps[64 * 64];
    int tid = threadIdx.x;
    int tx = tid & 15, ty = tid >> 4;
    int qt = blockIdx.x, h = blockIdx.y, b = blockIdx.z;

    const float* qbase = qkv + (size_t)(b * SEQ + qt * 64) * QKVD + h * HDIM;
    const float* kbase = qkv + (size_t)(b * SEQ) * QKVD + DM + h * HDIM;
    const float* vbase = kbase + DM;
    const float* biasrow = rel_bias + h * (2 * SEQ - 1);

    {
        int r = tid >> 2;
        int d0 = (tid & 3) << 4;
        const float* src = qbase + (size_t)r * QKVD + d0;
#pragma unroll
        for (int u = 0; u < 16; u += 4) {
            float4 v = *(const float4*)(src + u);
            Qt[(d0 + u + 0) * 64 + r] = v.x;
            Qt[(d0 + u + 1) * 64 + r] = v.y;
            Qt[(d0 + u + 2) * 64 + r] = v.z;
            Qt[(d0 + u + 3) * 64 + r] = v.w;
        }
    }

    float m[4], l[4], o[4][4];
#pragma unroll
    for (int i = 0; i < 4; i++) {
        m[i] = -1e30f;
        l[i] = 0.f;
#pragma unroll
        for (int c = 0; c < 4; c++) o[i][c] = 0.f;
    }

    for (int kt = 0; kt < 8; kt++) {
        __syncthreads();
        {
            int r = tid >> 2;
            int d0 = (tid & 3) << 4;
            const float* src = kbase + (size_t)(kt * 64 + r) * QKVD + d0;
#pragma unroll
            for (int u = 0; u < 16; u += 4) {
                float4 v = *(const float4*)(src + u);
                KVs[(d0 + u + 0) * 64 + r] = v.x;
                KVs[(d0 + u + 1) * 64 + r] = v.y;
                KVs[(d0 + u + 2) * 64 + r] = v.z;
                KVs[(d0 + u + 3) * 64 + r] = v.w;
            }
        }
        __syncthreads();

        float s[4][4];
#pragma unroll
        for (int i = 0; i < 4; i++)
#pragma unroll
            for (int j = 0; j < 4; j++) s[i][j] = 0.f;
#pragma unroll 16
        for (int d = 0; d < 64; d++) {
            float4 a = *(const float4*)&Qt[d * 64 + ty * 4];
            float4 bq = *(const float4*)&KVs[d * 64 + tx * 4];
            float aa[4] = {a.x, a.y, a.z, a.w};
            float bb[4] = {bq.x, bq.y, bq.z, bq.w};
#pragma unroll
            for (int i = 0; i < 4; i++)
#pragma unroll
                for (int j = 0; j < 4; j++) s[i][j] += aa[i] * bb[j];
        }

        int qg = qt * 64 + ty * 4;
        int kg = kt * 64 + tx * 4;
#pragma unroll
        for (int i = 0; i < 4; i++)
#pragma unroll
            for (int j = 0; j < 4; j++)
                s[i][j] = s[i][j] * 0.125f +
                          __ldg(&biasrow[(qg + i) - (kg + j) + (SEQ - 1)]);

        float mt[4];
#pragma unroll
        for (int i = 0; i < 4; i++) {
            mt[i] = fmaxf(fmaxf(s[i][0], s[i][1]), fmaxf(s[i][2], s[i][3]));
#pragma unroll
            for (int off = 8; off > 0; off >>= 1)
                mt[i] = fmaxf(mt[i], __shfl_xor_sync(0xffffffffu, mt[i], off, 16));
        }
        float fac[4];
#pragma unroll
        for (int i = 0; i < 4; i++) {
            float mn = fmaxf(m[i], mt[i]);
            fac[i] = __expf(m[i] - mn);
            m[i] = mn;
        }
        float rs[4];
#pragma unroll
        for (int i = 0; i < 4; i++) {
            rs[i] = 0.f;
#pragma unroll
            for (int j = 0; j < 4; j++) {
                float p = __expf(s[i][j] - m[i]);
                s[i][j] = p;
                rs[i] += p;
            }
#pragma unroll
            for (int off = 8; off > 0; off >>= 1)
                rs[i] += __shfl_xor_sync(0xffffffffu, rs[i], off, 16);
            l[i] = l[i] * fac[i] + rs[i];
#pragma unroll
            for (int c = 0; c < 4; c++) o[i][c] *= fac[i];
        }
#pragma unroll
        for (int i = 0; i < 4; i++)
            *(float4*)&Ps[(ty * 4 + i) * 64 + tx * 4] =
                make_float4(s[i][0], s[i][1], s[i][2], s[i][3]);
        __syncthreads();

        {
            int r = tid >> 2;
            int d0 = (tid & 3) << 4;
            const float* src = vbase + (size_t)(kt * 64 + r) * QKVD + d0;
#pragma unroll
            for (int u = 0; u < 16; u += 4)
                *(float4*)&KVs[r * 64 + d0 + u] = *(const float4*)(src + u);
        }
        __syncthreads();

#pragma unroll 16
        for (int j = 0; j < 64; j++) {
            float pa[4];
#pragma unroll
            for (int i = 0; i < 4; i++) pa[i] = Ps[(ty * 4 + i) * 64 + j];
            float4 vb = *(const float4*)&KVs[j * 64 + tx * 4];
            float vv[4] = {vb.x, vb.y, vb.z, vb.w};
#pragma unroll
            for (int i = 0; i < 4; i++)
#pragma unroll
                for (int c = 0; c < 4; c++) o[i][c] += pa[i] * vv[c];
        }
    }

    float* obase = attn_out + (size_t)(b * SEQ + qt * 64) * DM + h * HDIM;
#pragma unroll
    for (int i = 0; i < 4; i++) {
        float inv = 1.f / l[i];
        float4 rr = make_float4(o[i][0] * inv, o[i][1] * inv, o[i][2] * inv,
                                o[i][3] * inv);
        *(float4*)&obase[(size_t)(ty * 4 + i) * DM + tx * 4] = rr;
    }
}

// ---------------- launch ---------------------------------------------------
extern "C" void kernel_launch(void* const* d_in, const int* in_sizes, int n_in,
                              void* d_out, int out_size) {
    const float* x = (const float*)d_in[0];
    const float* in_w = (const float*)d_in[1];
    const float* in_b = (const float*)d_in[2];
    const float* out_w = (const float*)d_in[3];
    const float* out_b = (const float*)d_in[4];
    const float* rel_bias = (const float*)d_in[5];
    const float* w1 = (const float*)d_in[6];
    const float* b1 = (const float*)d_in[7];
    const float* w2 = (const float*)d_in[8];
    const float* b2 = (const float*)d_in[9];
    const float* ln1w = (const float*)d_in[10];
    const float* ln1b = (const float*)d_in[11];
    const float* ln2w = (const float*)d_in[12];
    const float* ln2b = (const float*)d_in[13];
    float* out = (float*)d_out;

    __nv_bfloat16 *wh, *wl, *xh, *xl, *ah, *al;
    float *qkv, *attn;
    cudaGetSymbolAddress((void**)&wh, g_wh);
    cudaGetSymbolAddress((void**)&wl, g_wl);
    cudaGetSymbolAddress((void**)&xh, g_xh);
    cudaGetSymbolAddress((void**)&xl, g_xl);
    cudaGetSymbolAddress((void**)&ah, g_ah);
    cudaGetSymbolAddress((void**)&al, g_al);
    cudaGetSymbolAddress((void**)&qkv, g_qkv);
    cudaGetSymbolAddress((void**)&attn, g_attn);

    cudaFuncSetAttribute(gemm_bf16x3<0>, cudaFuncAttributeMaxDynamicSharedMemorySize, SMEM_BYTES);
    cudaFuncSetAttribute(gemm_bf16x3<1>, cudaFuncAttributeMaxDynamicSharedMemorySize, SMEM_BYTES);
    cudaFuncSetAttribute(gemm_bf16x3<2>, cudaFuncAttributeMaxDynamicSharedMemorySize, SMEM_BYTES);

    const size_t OFF_INW = 0;
    const size_t OFF_OUTW = 3145728;
    const size_t OFF_W1 = 4194304;
    const size_t OFF_W2 = 8388608;

    cvt_pair<<<(3145728 / 4 + 255) / 256, 256>>>(in_w, wh + OFF_INW, wl + OFF_INW, 3145728 / 4);
    cvt_pair<<<(1048576 / 4 + 255) / 256, 256>>>(out_w, wh + OFF_OUTW, wl + OFF_OUTW, 1048576 / 4);
    cvt_pair<<<(4194304 / 4 + 255) / 256, 256>>>(w1, wh + OFF_W1, wl + OFF_W1, 4194304 / 4);
    cvt_pair<<<(4194304 / 4 + 255) / 256, 256>>>(w2, wh + OFF_W2, wl + OFF_W2, 4194304 / 4);

    // 1. xn = LN1(x) -> bf16 pair
    ln_pair_kernel<<<MROWS, 256>>>(x, ln1w, ln1b, xh, xl);
    // 2. qkv = xn @ in_proj_w^T + b
    gemm_bf16x3<0><<<dim3(QKVD / 128, MROWS / 128), 256, SMEM_BYTES>>>(
        xh, xl, wh + OFF_INW, wl + OFF_INW, in_b, nullptr, qkv, nullptr, nullptr,
        QKVD, DM);
    // 3. attention
    attn_kernel<<<dim3(SEQ / 64, NH, BSZ), 256>>>(qkv, rel_bias, attn);
    // 3b. attn -> bf16 pair
    cvt_pair<<<((MROWS * DM) / 4 + 255) / 256, 256>>>(attn, xh, xl, (MROWS * DM) / 4);
    // 4. out = x + attn @ out_w^T + b
    gemm_bf16x3<2><<<dim3(DM / 128, MROWS / 128), 256, SMEM_BYTES>>>(
        xh, xl, wh + OFF_OUTW, wl + OFF_OUTW, out_b, x, out, nullptr, nullptr,
        DM, DM);
    // 5. xn = LN2(out) -> bf16 pair
    ln_pair_kernel<<<MROWS, 256>>>(out, ln2w, ln2b, xh, xl);
    // 6. ffn = gelu(xn @ w1^T + b1) -> bf16 pair
    gemm_bf16x3<1><<<dim3(DFF / 128, MROWS / 128), 256, SMEM_BYTES>>>(
        xh, xl, wh + OFF_W1, wl + OFF_W1, b1, nullptr, nullptr, ah, al,
        DFF, DM);
    // 7. out = out + ffn @ w2^T + b2
    gemm_bf16x3<2><<<dim3(DM / 128, MROWS / 128), 256, SMEM_BYTES>>>(
        ah, al, wh + OFF_W2, wl + OFF_W2, b2, out, out, nullptr, nullptr,
        DM, DFF);
}

// round 7
// speedup vs baseline: 2.1819x; 1.0834x over previous
#include <cuda_runtime.h>
#include <cuda_bf16.h>
#include <math.h>
#include <stdint.h>

#define BSZ 16
#define SEQ 512
#define DM 1024
#define NH 16
#define HDIM 64
#define DFF 4096
#define MROWS (BSZ * SEQ)  // 8192
#define QKVD (3 * DM)      // 3072

// ---------------- scratch (device globals; no cudaMalloc allowed) ----------
__device__ __align__(16) __nv_bfloat16 g_wh[12582912];            // weights hi
__device__ __align__(16) __nv_bfloat16 g_wl[12582912];            // weights lo
__device__ __align__(16) __nv_bfloat16 g_xh[(size_t)MROWS * DM];  // act pair
__device__ __align__(16) __nv_bfloat16 g_xl[(size_t)MROWS * DM];
__device__ __align__(16) __nv_bfloat16 g_ah[(size_t)MROWS * DFF]; // ffn pair
__device__ __align__(16) __nv_bfloat16 g_al[(size_t)MROWS * DFF];
__device__ float g_qkv[(size_t)MROWS * QKVD];

// ---------------- PTX helpers ----------------------------------------------
__device__ __forceinline__ uint32_t s2u(const void* p) {
    uint32_t a;
    asm("{ .reg .u64 t; cvta.to.shared.u64 t, %1; cvt.u32.u64 %0, t; }"
        : "=r"(a) : "l"(p));
    return a;
}
__device__ __forceinline__ void cp_async16(uint32_t dst, const void* src) {
    asm volatile("cp.async.cg.shared.global [%0], [%1], 16;"
                 :: "r"(dst), "l"(src) : "memory");
}
__device__ __forceinline__ void cp_commit() {
    asm volatile("cp.async.commit_group;" ::: "memory");
}
template <int N>
__device__ __forceinline__ void cp_wait() {
    asm volatile("cp.async.wait_group %0;" :: "n"(N) : "memory");
}
#define LDSM4(d, a) \
    asm volatile("ldmatrix.sync.aligned.m8n8.x4.shared.b16 {%0,%1,%2,%3}, [%4];" \
                 : "=r"((d)[0]), "=r"((d)[1]), "=r"((d)[2]), "=r"((d)[3]) : "r"(a))
#define MMA16816(c, a, b) \
    asm volatile( \
        "mma.sync.aligned.m16n8k16.row.col.f32.bf16.bf16.f32 " \
        "{%0,%1,%2,%3},{%4,%5,%6,%7},{%8,%9},{%0,%1,%2,%3};" \
        : "+f"((c)[0]), "+f"((c)[1]), "+f"((c)[2]), "+f"((c)[3]) \
        : "r"((a)[0]), "r"((a)[1]), "r"((a)[2]), "r"((a)[3]), \
          "r"((b)[0]), "r"((b)[1]))

// SMEM tile geometry: 128 rows x 32 bf16 data, 80-byte row stride (pad 8)
#define ROWB 80
#define TILEB (128 * ROWB)      // 10240
#define STAGEB (4 * TILEB)      // 40960
#define NSTAGE 4
#define SMEM_BYTES (NSTAGE * STAGEB)  // 163840

__device__ __forceinline__ float gelu_f(float v) {
    return 0.5f * v * (1.f + erff(v * 0.70710678118654752f));
}
__device__ __forceinline__ void split_pair(float v, __nv_bfloat16& h, __nv_bfloat16& l) {
    h = __float2bfloat16(v);
    l = __float2bfloat16(v - __bfloat162float(h));
}

// ---------------- convert fp32 -> bf16 hi/lo pair --------------------------
__global__ void cvt_pair(const float* __restrict__ in, __nv_bfloat16* __restrict__ oh,
                         __nv_bfloat16* __restrict__ ol, int n4) {
    int i = blockIdx.x * blockDim.x + threadIdx.x;
    if (i >= n4) return;
    float4 v = ((const float4*)in)[i];
    __nv_bfloat162 h0, h1, l0, l1;
    split_pair(v.x, h0.x, l0.x);
    split_pair(v.y, h0.y, l0.y);
    split_pair(v.z, h1.x, l1.x);
    split_pair(v.w, h1.y, l1.y);
    ((__nv_bfloat162*)oh)[i * 2] = h0;
    ((__nv_bfloat162*)oh)[i * 2 + 1] = h1;
    ((__nv_bfloat162*)ol)[i * 2] = l0;
    ((__nv_bfloat162*)ol)[i * 2 + 1] = l1;
}

// ---------------- LayerNorm -> bf16 hi/lo pair -----------------------------
__global__ void ln_pair_kernel(const float* __restrict__ x, const float* __restrict__ w,
                               const float* __restrict__ b, __nv_bfloat16* __restrict__ oh,
                               __nv_bfloat16* __restrict__ ol) {
    int row = blockIdx.x;
    int tid = threadIdx.x;
    const float4* xr = (const float4*)(x + (size_t)row * DM);
    float4 v = xr[tid];
    float s = v.x + v.y + v.z + v.w;
    float s2 = v.x * v.x + v.y * v.y + v.z * v.z + v.w * v.w;
    __shared__ float red[16];
#pragma unroll
    for (int off = 16; off > 0; off >>= 1) {
        s += __shfl_xor_sync(0xffffffffu, s, off);
        s2 += __shfl_xor_sync(0xffffffffu, s2, off);
    }
    int wid = tid >> 5;
    if ((tid & 31) == 0) { red[wid] = s; red[8 + wid] = s2; }
    __syncthreads();
    if (tid < 32) {
        s = (tid < 8) ? red[tid] : 0.f;
        s2 = (tid < 8) ? red[8 + tid] : 0.f;
#pragma unroll
        for (int off = 4; off > 0; off >>= 1) {
            s += __shfl_xor_sync(0xffffffffu, s, off);
            s2 += __shfl_xor_sync(0xffffffffu, s2, off);
        }
        if (tid == 0) {
            float mu = s * (1.f / DM);
            float var = s2 * (1.f / DM) - mu * mu;
            red[0] = mu;
            red[1] = rsqrtf(var + 1e-5f);
        }
    }
    __syncthreads();
    float mu = red[0], rstd = red[1];
    float4 wv = ((const float4*)w)[tid];
    float4 bv = ((const float4*)b)[tid];
    float4 o;
    o.x = (v.x - mu) * rstd * wv.x + bv.x;
    o.y = (v.y - mu) * rstd * wv.y + bv.y;
    o.z = (v.z - mu) * rstd * wv.z + bv.z;
    o.w = (v.w - mu) * rstd * wv.w + bv.w;
    __nv_bfloat162 h0, h1, l0, l1;
    split_pair(o.x, h0.x, l0.x);
    split_pair(o.y, h0.y, l0.y);
    split_pair(o.z, h1.x, l1.x);
    split_pair(o.w, h1.y, l1.y);
    size_t base = (size_t)row * DM;
    ((__nv_bfloat162*)(oh + base))[tid * 2] = h0;
    ((__nv_bfloat162*)(oh + base))[tid * 2 + 1] = h1;
    ((__nv_bfloat162*)(ol + base))[tid * 2] = l0;
    ((__nv_bfloat162*)(ol + base))[tid * 2 + 1] = l1;
}

// ---------------- bf16x3 GEMM via mma.sync, 4-stage cp.async ---------------
// C[M,N] = A*W^T (+bias, EPI). A=Ah+Al, W=Wh+Wl (K-major).
// 128x128 CTA tile, BK=32, 256 thr, warp tile 32x64.
// EPI: 0 = bias -> Cf; 1 = gelu(bias+acc) -> (Oh,Ol); 2 = res+bias+acc -> Cf
template <int EPI>
__global__ void __launch_bounds__(256, 1) gemm_bf16x3(
    const __nv_bfloat16* __restrict__ Ah, const __nv_bfloat16* __restrict__ Al,
    const __nv_bfloat16* __restrict__ Wh, const __nv_bfloat16* __restrict__ Wl,
    const float* __restrict__ bias, const float* __restrict__ res,
    float* __restrict__ Cf, __nv_bfloat16* __restrict__ Oh,
    __nv_bfloat16* __restrict__ Ol, int N, int K) {
    extern __shared__ char smem[];
    uint32_t sbase = s2u(smem);
    int tid = threadIdx.x;
    int w = tid >> 5, lane = tid & 31;
    int bm = blockIdx.y, bn = blockIdx.x;
    int mbase = (w & 3) * 32, nbase = (w >> 2) * 64;

    const __nv_bfloat16* tsrc[4];
    tsrc[0] = Ah + (size_t)bm * 128 * K;
    tsrc[1] = Al + (size_t)bm * 128 * K;
    tsrc[2] = Wh + (size_t)bn * 128 * K;
    tsrc[3] = Wl + (size_t)bn * 128 * K;

    int r0 = tid >> 2, c0 = tid & 3;
    int r1 = (tid + 256) >> 2, c1 = tid & 3;

    int g = lane >> 3, lr = lane & 7;
    uint32_t offA = (uint32_t)((mbase + (g & 1) * 8 + lr) * ROWB + (g >> 1) * 16);
    uint32_t offB = (uint32_t)((nbase + (g >> 1) * 8 + lr) * ROWB + (g & 1) * 16);

    float acc[2][8][4];
#pragma unroll
    for (int mt = 0; mt < 2; mt++)
#pragma unroll
        for (int nt = 0; nt < 8; nt++)
#pragma unroll
            for (int u = 0; u < 4; u++) acc[mt][nt][u] = 0.f;

    int NK = K >> 5;  // BK = 32; NK >= 32 always here

    // prologue: stages 0..2, one commit group per stage
#pragma unroll
    for (int s = 0; s < NSTAGE - 1; s++) {
        uint32_t sb = sbase + s * STAGEB;
        int k0 = s << 5;
#pragma unroll
        for (int t = 0; t < 4; t++) {
            cp_async16(sb + t * TILEB + r0 * ROWB + c0 * 16,
                       tsrc[t] + (size_t)r0 * K + k0 + c0 * 8);
            cp_async16(sb + t * TILEB + r1 * ROWB + c1 * 16,
                       tsrc[t] + (size_t)r1 * K + k0 + c1 * 8);
        }
        cp_commit();
    }

    for (int k = 0; k < NK; k++) {
        // group index == stage index (commit every iter); ensure stage k done
        cp_wait<NSTAGE - 2>();
        __syncthreads();  // all warps done with chunk k-1 -> buf (k-1)&3 free

        // issue loads for stage k+3 into buf (k+3)&3 (== (k-1)&3)
        if (k + NSTAGE - 1 < NK) {
            uint32_t sb = sbase + ((k + NSTAGE - 1) & (NSTAGE - 1)) * STAGEB;
            int k0 = (k + NSTAGE - 1) << 5;
#pragma unroll
            for (int t = 0; t < 4; t++) {
                cp_async16(sb + t * TILEB + r0 * ROWB + c0 * 16,
                           tsrc[t] + (size_t)r0 * K + k0 + c0 * 8);
                cp_async16(sb + t * TILEB + r1 * ROWB + c1 * 16,
                           tsrc[t] + (size_t)r1 * K + k0 + c1 * 8);
            }
        }
        cp_commit();  // always commit (empty groups keep indices aligned)

        uint32_t sb = sbase + (k & (NSTAGE - 1)) * STAGEB;
        uint32_t aAh = sb + offA, aAl = sb + TILEB + offA;
        uint32_t aBh = sb + 2 * TILEB + offB, aBl = sb + 3 * TILEB + offB;

#pragma unroll
        for (int ks = 0; ks < 2; ks++) {
            uint32_t ko = ks * 32;
            uint32_t ah[2][4], al[2][4];
            LDSM4(ah[0], aAh + ko);
            LDSM4(ah[1], aAh + ko + 16 * ROWB);
            LDSM4(al[0], aAl + ko);
            LDSM4(al[1], aAl + ko + 16 * ROWB);
            uint32_t bh[8][2], bl[8][2];
#pragma unroll
            for (int p = 0; p < 4; p++) {
                uint32_t q[4];
                LDSM4(q, aBh + ko + p * (16 * ROWB));
                bh[2 * p][0] = q[0]; bh[2 * p][1] = q[1];
                bh[2 * p + 1][0] = q[2]; bh[2 * p + 1][1] = q[3];
                LDSM4(q, aBl + ko + p * (16 * ROWB));
                bl[2 * p][0] = q[0]; bl[2 * p][1] = q[1];
                bl[2 * p + 1][0] = q[2]; bl[2 * p + 1][1] = q[3];
            }
#pragma unroll
            for (int mt = 0; mt < 2; mt++)
#pragma unroll
                for (int nt = 0; nt < 8; nt++) {
                    MMA16816(acc[mt][nt], ah[mt], bh[nt]);
                    MMA16816(acc[mt][nt], ah[mt], bl[nt]);
                    MMA16816(acc[mt][nt], al[mt], bh[nt]);
                }
        }
    }

    // ---------------- epilogue (registers only) ----------------
    int l4 = lane >> 2, l2 = (lane & 3) * 2;
#pragma unroll
    for (int mt = 0; mt < 2; mt++) {
        int row = bm * 128 + mbase + mt * 16 + l4;
#pragma unroll
        for (int nt = 0; nt < 8; nt++) {
            int col = bn * 128 + nbase + nt * 8 + l2;
            float2 bv = *(const float2*)(bias + col);
            float v0 = acc[mt][nt][0] + bv.x;
            float v1 = acc[mt][nt][1] + bv.y;
            float v2 = acc[mt][nt][2] + bv.x;
            float v3 = acc[mt][nt][3] + bv.y;
            size_t p0 = (size_t)row * N + col;
            size_t p1 = (size_t)(row + 8) * N + col;
            if (EPI == 2) {
                float2 rv0 = *(const float2*)(res + p0);
                float2 rv1 = *(const float2*)(res + p1);
                v0 += rv0.x; v1 += rv0.y; v2 += rv1.x; v3 += rv1.y;
            }
            if (EPI == 1) {
                v0 = gelu_f(v0); v1 = gelu_f(v1);
                v2 = gelu_f(v2); v3 = gelu_f(v3);
                __nv_bfloat162 hp0, hp1, lp0, lp1;
                split_pair(v0, hp0.x, lp0.x);
                split_pair(v1, hp0.y, lp0.y);
                split_pair(v2, hp1.x, lp1.x);
                split_pair(v3, hp1.y, lp1.y);
                *(__nv_bfloat162*)(Oh + p0) = hp0;
                *(__nv_bfloat162*)(Oh + p1) = hp1;
                *(__nv_bfloat162*)(Ol + p0) = lp0;
                *(__nv_bfloat162*)(Ol + p1) = lp1;
            } else {
                *(float2*)(Cf + p0) = make_float2(v0, v1);
                *(float2*)(Cf + p1) = make_float2(v2, v3);
            }
        }
    }
}

// ---------------- Flash-style attention (fp32) -> bf16 pair output ---------
__global__ __launch_bounds__(256, 4) void attn_kernel(
    const float* __restrict__ qkv, const float* __restrict__ rel_bias,
    __nv_bfloat16* __restrict__ oh, __nv_bfloat16* __restrict__ ol) {
    __shared__ float Qt[64 * 64];
    __shared__ float KVs[64 * 64];
    __shared__ float Ps[64 * 64];
    int tid = threadIdx.x;
    int tx = tid & 15, ty = tid >> 4;
    int qt = blockIdx.x, h = blockIdx.y, b = blockIdx.z;

    const float* qbase = qkv + (size_t)(b * SEQ + qt * 64) * QKVD + h * HDIM;
    const float* kbase = qkv + (size_t)(b * SEQ) * QKVD + DM + h * HDIM;
    const float* vbase = kbase + DM;
    const float* biasrow = rel_bias + h * (2 * SEQ - 1);

    {
        int r = tid >> 2;
        int d0 = (tid & 3) << 4;
        const float* src = qbase + (size_t)r * QKVD + d0;
#pragma unroll
        for (int u = 0; u < 16; u += 4) {
            float4 v = *(const float4*)(src + u);
            Qt[(d0 + u + 0) * 64 + r] = v.x;
            Qt[(d0 + u + 1) * 64 + r] = v.y;
            Qt[(d0 + u + 2) * 64 + r] = v.z;
            Qt[(d0 + u + 3) * 64 + r] = v.w;
        }
    }

    float m[4], l[4], o[4][4];
#pragma unroll
    for (int i = 0; i < 4; i++) {
        m[i] = -1e30f;
        l[i] = 0.f;
#pragma unroll
        for (int c = 0; c < 4; c++) o[i][c] = 0.f;
    }

    for (int kt = 0; kt < 8; kt++) {
        __syncthreads();
        {
            int r = tid >> 2;
            int d0 = (tid & 3) << 4;
            const float* src = kbase + (size_t)(kt * 64 + r) * QKVD + d0;
#pragma unroll
            for (int u = 0; u < 16; u += 4) {
                float4 v = *(const float4*)(src + u);
                KVs[(d0 + u + 0) * 64 + r] = v.x;
                KVs[(d0 + u + 1) * 64 + r] = v.y;
                KVs[(d0 + u + 2) * 64 + r] = v.z;
                KVs[(d0 + u + 3) * 64 + r] = v.w;
            }
        }
        __syncthreads();

        float s[4][4];
#pragma unroll
        for (int i = 0; i < 4; i++)
#pragma unroll
            for (int j = 0; j < 4; j++) s[i][j] = 0.f;
#pragma unroll 16
        for (int d = 0; d < 64; d++) {
            float4 a = *(const float4*)&Qt[d * 64 + ty * 4];
            float4 bq = *(const float4*)&KVs[d * 64 + tx * 4];
            float aa[4] = {a.x, a.y, a.z, a.w};
            float bb[4] = {bq.x, bq.y, bq.z, bq.w};
#pragma unroll
            for (int i = 0; i < 4; i++)
#pragma unroll
                for (int j = 0; j < 4; j++) s[i][j] += aa[i] * bb[j];
        }

        int qg = qt * 64 + ty * 4;
        int kg = kt * 64 + tx * 4;
#pragma unroll
        for (int i = 0; i < 4; i++)
#pragma unroll
            for (int j = 0; j < 4; j++)
                s[i][j] = s[i][j] * 0.125f +
                          __ldg(&biasrow[(qg + i) - (kg + j) + (SEQ - 1)]);

        float mt[4];
#pragma unroll
        for (int i = 0; i < 4; i++) {
            mt[i] = fmaxf(fmaxf(s[i][0], s[i][1]), fmaxf(s[i][2], s[i][3]));
#pragma unroll
            for (int off = 8; off > 0; off >>= 1)
                mt[i] = fmaxf(mt[i], __shfl_xor_sync(0xffffffffu, mt[i], off, 16));
        }
        float fac[4];
#pragma unroll
        for (int i = 0; i < 4; i++) {
            float mn = fmaxf(m[i], mt[i]);
            fac[i] = __expf(m[i] - mn);
            m[i] = mn;
        }
        float rs[4];
#pragma unroll
        for (int i = 0; i < 4; i++) {
            rs[i] = 0.f;
#pragma unroll
            for (int j = 0; j < 4; j++) {
                float p = __expf(s[i][j] - m[i]);
                s[i][j] = p;
                rs[i] += p;
            }
#pragma unroll
            for (int off = 8; off > 0; off >>= 1)
                rs[i] += __shfl_xor_sync(0xffffffffu, rs[i], off, 16);
            l[i] = l[i] * fac[i] + rs[i];
#pragma unroll
            for (int c = 0; c < 4; c++) o[i][c] *= fac[i];
        }
#pragma unroll
        for (int i = 0; i < 4; i++)
            *(float4*)&Ps[(ty * 4 + i) * 64 + tx * 4] =
                make_float4(s[i][0], s[i][1], s[i][2], s[i][3]);
        __syncthreads();

        {
            int r = tid >> 2;
            int d0 = (tid & 3) << 4;
            const float* src = vbase + (size_t)(kt * 64 + r) * QKVD + d0;
#pragma unroll
            for (int u = 0; u < 16; u += 4)
                *(float4*)&KVs[r * 64 + d0 + u] = *(const float4*)(src + u);
        }
        __syncthreads();

#pragma unroll 16
        for (int j = 0; j < 64; j++) {
            float pa[4];
#pragma unroll
            for (int i = 0; i < 4; i++) pa[i] = Ps[(ty * 4 + i) * 64 + j];
            float4 vb = *(const float4*)&KVs[j * 64 + tx * 4];
            float vv[4] = {vb.x, vb.y, vb.z, vb.w};
#pragma unroll
            for (int i = 0; i < 4; i++)
#pragma unroll
                for (int c = 0; c < 4; c++) o[i][c] += pa[i] * vv[c];
        }
    }

    // write bf16 hi/lo pair directly (skip fp32 round trip + cvt pass)
    size_t obase = (size_t)(b * SEQ + qt * 64) * DM + h * HDIM;
#pragma unroll
    for (int i = 0; i < 4; i++) {
        float inv = 1.f / l[i];
        float v0 = o[i][0] * inv, v1 = o[i][1] * inv;
        float v2 = o[i][2] * inv, v3 = o[i][3] * inv;
        __nv_bfloat162 hp0, hp1, lp0, lp1;
        split_pair(v0, hp0.x, lp0.x);
        split_pair(v1, hp0.y, lp0.y);
        split_pair(v2, hp1.x, lp1.x);
        split_pair(v3, hp1.y, lp1.y);
        size_t p = obase + (size_t)(ty * 4 + i) * DM + tx * 4;
        *(__nv_bfloat162*)(oh + p) = hp0;
        *(__nv_bfloat162*)(oh + p + 2) = hp1;
        *(__nv_bfloat162*)(ol + p) = lp0;
        *(__nv_bfloat162*)(ol + p + 2) = lp1;
    }
}

// ---------------- launch ---------------------------------------------------
extern "C" void kernel_launch(void* const* d_in, const int* in_sizes, int n_in,
                              void* d_out, int out_size) {
    const float* x = (const float*)d_in[0];
    const float* in_w = (const float*)d_in[1];
    const float* in_b = (const float*)d_in[2];
    const float* out_w = (const float*)d_in[3];
    const float* out_b = (const float*)d_in[4];
    const float* rel_bias = (const float*)d_in[5];
    const float* w1 = (const float*)d_in[6];
    const float* b1 = (const float*)d_in[7];
    const float* w2 = (const float*)d_in[8];
    const float* b2 = (const float*)d_in[9];
    const float* ln1w = (const float*)d_in[10];
    const float* ln1b = (const float*)d_in[11];
    const float* ln2w = (const float*)d_in[12];
    const float* ln2b = (const float*)d_in[13];
    float* out = (float*)d_out;

    __nv_bfloat16 *wh, *wl, *xh, *xl, *ah, *al;
    float* qkv;
    cudaGetSymbolAddress((void**)&wh, g_wh);
    cudaGetSymbolAddress((void**)&wl, g_wl);
    cudaGetSymbolAddress((void**)&xh, g_xh);
    cudaGetSymbolAddress((void**)&xl, g_xl);
    cudaGetSymbolAddress((void**)&ah, g_ah);
    cudaGetSymbolAddress((void**)&al, g_al);
    cudaGetSymbolAddress((void**)&qkv, g_qkv);

    cudaFuncSetAttribute(gemm_bf16x3<0>, cudaFuncAttributeMaxDynamicSharedMemorySize, SMEM_BYTES);
    cudaFuncSetAttribute(gemm_bf16x3<1>, cudaFuncAttributeMaxDynamicSharedMemorySize, SMEM_BYTES);
    cudaFuncSetAttribute(gemm_bf16x3<2>, cudaFuncAttributeMaxDynamicSharedMemorySize, SMEM_BYTES);

    const size_t OFF_INW = 0;
    const size_t OFF_OUTW = 3145728;
    const size_t OFF_W1 = 4194304;
    const size_t OFF_W2 = 8388608;

    cvt_pair<<<(3145728 / 4 + 255) / 256, 256>>>(in_w, wh + OFF_INW, wl + OFF_INW, 3145728 / 4);
    cvt_pair<<<(1048576 / 4 + 255) / 256, 256>>>(out_w, wh + OFF_OUTW, wl + OFF_OUTW, 1048576 / 4);
    cvt_pair<<<(4194304 / 4 + 255) / 256, 256>>>(w1, wh + OFF_W1, wl + OFF_W1, 4194304 / 4);
    cvt_pair<<<(4194304 / 4 + 255) / 256, 256>>>(w2, wh + OFF_W2, wl + OFF_W2, 4194304 / 4);

    // 1. xn = LN1(x) -> bf16 pair
    ln_pair_kernel<<<MROWS, 256>>>(x, ln1w, ln1b, xh, xl);
    // 2. qkv = xn @ in_proj_w^T + b
    gemm_bf16x3<0><<<dim3(QKVD / 128, MROWS / 128), 256, SMEM_BYTES>>>(
        xh, xl, wh + OFF_INW, wl + OFF_INW, in_b, nullptr, qkv, nullptr, nullptr,
        QKVD, DM);
    // 3. attention -> bf16 pair (fused)
    attn_kernel<<<dim3(SEQ / 64, NH, BSZ), 256>>>(qkv, rel_bias, xh, xl);
    // 4. out = x + attn @ out_w^T + b
    gemm_bf16x3<2><<<dim3(DM / 128, MROWS / 128), 256, SMEM_BYTES>>>(
        xh, xl, wh + OFF_OUTW, wl + OFF_OUTW, out_b, x, out, nullptr, nullptr,
        DM, DM);
    // 5. xn = LN2(out) -> bf16 pair
    ln_pair_kernel<<<MROWS, 256>>>(out, ln2w, ln2b, xh, xl);
    // 6. ffn = gelu(xn @ w1^T + b1) -> bf16 pair
    gemm_bf16x3<1><<<dim3(DFF / 128, MROWS / 128), 256, SMEM_BYTES>>>(
        xh, xl, wh + OFF_W1, wl + OFF_W1, b1, nullptr, nullptr, ah, al,
        DFF, DM);
    // 7. out = out + ffn @ w2^T + b2
    gemm_bf16x3<2><<<dim3(DM / 128, MROWS / 128), 256, SMEM_BYTES>>>(
        ah, al, wh + OFF_W2, wl + OFF_W2, b2, out, out, nullptr, nullptr,
        DM, DFF);
}

// round 8
// speedup vs baseline: 2.2511x; 1.0317x over previous
#include <cuda_runtime.h>
#include <cuda_bf16.h>
#include <math.h>
#include <stdint.h>

#define BSZ 16
#define SEQ 512
#define DM 1024
#define NH 16
#define HDIM 64
#define DFF 4096
#define MROWS (BSZ * SEQ)  // 8192
#define QKVD (3 * DM)      // 3072

// ---------------- scratch (device globals; no cudaMalloc allowed) ----------
__device__ __align__(16) __nv_bfloat16 g_wh[12582912];            // weights hi
__device__ __align__(16) __nv_bfloat16 g_wl[12582912];            // weights lo
__device__ __align__(16) __nv_bfloat16 g_xh[(size_t)MROWS * DM];  // act pair
__device__ __align__(16) __nv_bfloat16 g_xl[(size_t)MROWS * DM];
__device__ __align__(16) __nv_bfloat16 g_ah[(size_t)MROWS * DFF]; // ffn pair
__device__ __align__(16) __nv_bfloat16 g_al[(size_t)MROWS * DFF];
__device__ float g_qkv[(size_t)MROWS * QKVD];

// ---------------- PTX helpers ----------------------------------------------
__device__ __forceinline__ uint32_t s2u(const void* p) {
    uint32_t a;
    asm("{ .reg .u64 t; cvta.to.shared.u64 t, %1; cvt.u32.u64 %0, t; }"
        : "=r"(a) : "l"(p));
    return a;
}
__device__ __forceinline__ void cp_async16(uint32_t dst, const void* src) {
    asm volatile("cp.async.cg.shared.global [%0], [%1], 16;"
                 :: "r"(dst), "l"(src) : "memory");
}
__device__ __forceinline__ void cp_commit() {
    asm volatile("cp.async.commit_group;" ::: "memory");
}
template <int N>
__device__ __forceinline__ void cp_wait() {
    asm volatile("cp.async.wait_group %0;" :: "n"(N) : "memory");
}
#define LDSM4(d, a) \
    asm volatile("ldmatrix.sync.aligned.m8n8.x4.shared.b16 {%0,%1,%2,%3}, [%4];" \
                 : "=r"((d)[0]), "=r"((d)[1]), "=r"((d)[2]), "=r"((d)[3]) : "r"(a))
#define MMA16816(c, a, b0, b1) \
    asm volatile( \
        "mma.sync.aligned.m16n8k16.row.col.f32.bf16.bf16.f32 " \
        "{%0,%1,%2,%3},{%4,%5,%6,%7},{%8,%9},{%0,%1,%2,%3};" \
        : "+f"((c)[0]), "+f"((c)[1]), "+f"((c)[2]), "+f"((c)[3]) \
        : "r"((a)[0]), "r"((a)[1]), "r"((a)[2]), "r"((a)[3]), \
          "r"(b0), "r"(b1))

// SMEM tile geometry: rows x 32 bf16 data, 80-byte row stride (pad 8)
#define ROWB 80
#define TILEA (128 * ROWB)        // 10240 (A: 128 rows)
#define TILEBB (256 * ROWB)       // 20480 (B: 256 rows)
#define STAGEB (2 * TILEA + 2 * TILEBB)  // 61440
#define NSTAGE 3
#define SMEM_BYTES (NSTAGE * STAGEB)     // 184320

__device__ __forceinline__ float gelu_f(float v) {
    return 0.5f * v * (1.f + erff(v * 0.70710678118654752f));
}
__device__ __forceinline__ void split_pair(float v, __nv_bfloat16& h, __nv_bfloat16& l) {
    h = __float2bfloat16(v);
    l = __float2bfloat16(v - __bfloat162float(h));
}

// ---------------- convert fp32 -> bf16 hi/lo pair --------------------------
__global__ void cvt_pair(const float* __restrict__ in, __nv_bfloat16* __restrict__ oh,
                         __nv_bfloat16* __restrict__ ol, int n4) {
    int i = blockIdx.x * blockDim.x + threadIdx.x;
    if (i >= n4) return;
    float4 v = ((const float4*)in)[i];
    __nv_bfloat162 h0, h1, l0, l1;
    split_pair(v.x, h0.x, l0.x);
    split_pair(v.y, h0.y, l0.y);
    split_pair(v.z, h1.x, l1.x);
    split_pair(v.w, h1.y, l1.y);
    ((__nv_bfloat162*)oh)[i * 2] = h0;
    ((__nv_bfloat162*)oh)[i * 2 + 1] = h1;
    ((__nv_bfloat162*)ol)[i * 2] = l0;
    ((__nv_bfloat162*)ol)[i * 2 + 1] = l1;
}

// ---------------- LayerNorm -> bf16 hi/lo pair -----------------------------
__global__ void ln_pair_kernel(const float* __restrict__ x, const float* __restrict__ w,
                               const float* __restrict__ b, __nv_bfloat16* __restrict__ oh,
                               __nv_bfloat16* __restrict__ ol) {
    int row = blockIdx.x;
    int tid = threadIdx.x;
    const float4* xr = (const float4*)(x + (size_t)row * DM);
    float4 v = xr[tid];
    float s = v.x + v.y + v.z + v.w;
    float s2 = v.x * v.x + v.y * v.y + v.z * v.z + v.w * v.w;
    __shared__ float red[16];
#pragma unroll
    for (int off = 16; off > 0; off >>= 1) {
        s += __shfl_xor_sync(0xffffffffu, s, off);
        s2 += __shfl_xor_sync(0xffffffffu, s2, off);
    }
    int wid = tid >> 5;
    if ((tid & 31) == 0) { red[wid] = s; red[8 + wid] = s2; }
    __syncthreads();
    if (tid < 32) {
        s = (tid < 8) ? red[tid] : 0.f;
        s2 = (tid < 8) ? red[8 + tid] : 0.f;
#pragma unroll
        for (int off = 4; off > 0; off >>= 1) {
            s += __shfl_xor_sync(0xffffffffu, s, off);
            s2 += __shfl_xor_sync(0xffffffffu, s2, off);
        }
        if (tid == 0) {
            float mu = s * (1.f / DM);
            float var = s2 * (1.f / DM) - mu * mu;
            red[0] = mu;
            red[1] = rsqrtf(var + 1e-5f);
        }
    }
    __syncthreads();
    float mu = red[0], rstd = red[1];
    float4 wv = ((const float4*)w)[tid];
    float4 bv = ((const float4*)b)[tid];
    float4 o;
    o.x = (v.x - mu) * rstd * wv.x + bv.x;
    o.y = (v.y - mu) * rstd * wv.y + bv.y;
    o.z = (v.z - mu) * rstd * wv.z + bv.z;
    o.w = (v.w - mu) * rstd * wv.w + bv.w;
    __nv_bfloat162 h0, h1, l0, l1;
    split_pair(o.x, h0.x, l0.x);
    split_pair(o.y, h0.y, l0.y);
    split_pair(o.z, h1.x, l1.x);
    split_pair(o.w, h1.y, l1.y);
    size_t base = (size_t)row * DM;
    ((__nv_bfloat162*)(oh + base))[tid * 2] = h0;
    ((__nv_bfloat162*)(oh + base))[tid * 2 + 1] = h1;
    ((__nv_bfloat162*)(ol + base))[tid * 2] = l0;
    ((__nv_bfloat162*)(ol + base))[tid * 2 + 1] = l1;
}

// ---------------- bf16x3 GEMM via mma.sync, 128x256 tile, 3-stage ----------
// C[M,N] = A*W^T (+bias, EPI). A=Ah+Al, W=Wh+Wl (K-major).
// CTA tile 128x256, BK=32, 256 thr, warp tile 64x64 (2m x 4n warps).
// EPI: 0 = bias -> Cf; 1 = gelu(bias+acc) -> (Oh,Ol); 2 = res+bias+acc -> Cf
template <int EPI>
__global__ void __launch_bounds__(256, 1) gemm_bf16x3(
    const __nv_bfloat16* __restrict__ Ah, const __nv_bfloat16* __restrict__ Al,
    const __nv_bfloat16* __restrict__ Wh, const __nv_bfloat16* __restrict__ Wl,
    const float* __restrict__ bias, const float* __restrict__ res,
    float* __restrict__ Cf, __nv_bfloat16* __restrict__ Oh,
    __nv_bfloat16* __restrict__ Ol, int N, int K) {
    extern __shared__ char smem[];
    uint32_t sbase = s2u(smem);
    int tid = threadIdx.x;
    int w = tid >> 5, lane = tid & 31;
    int bm = blockIdx.y, bn = blockIdx.x;
    int mbase = (w & 1) * 64, nbase = (w >> 1) * 64;

    const __nv_bfloat16* srcA[2];
    const __nv_bfloat16* srcB[2];
    srcA[0] = Ah + (size_t)bm * 128 * K;
    srcA[1] = Al + (size_t)bm * 128 * K;
    srcB[0] = Wh + (size_t)bn * 256 * K;
    srcB[1] = Wl + (size_t)bn * 256 * K;

    int g = lane >> 3, lr = lane & 7;
    uint32_t offA = (uint32_t)((mbase + (g & 1) * 8 + lr) * ROWB + (g >> 1) * 16);
    uint32_t offB = (uint32_t)((nbase + (g >> 1) * 8 + lr) * ROWB + (g & 1) * 16);

    float acc[4][8][4];
#pragma unroll
    for (int mt = 0; mt < 4; mt++)
#pragma unroll
        for (int nt = 0; nt < 8; nt++)
#pragma unroll
            for (int u = 0; u < 4; u++) acc[mt][nt][u] = 0.f;

    int NK = K >> 5;  // BK = 32

    // stage loader: stage s -> buffer buf
#define LOAD_STAGE(s_, buf_)                                                   \
    do {                                                                       \
        uint32_t sb_ = sbase + (buf_) * STAGEB;                                \
        int k0_ = (s_) << 5;                                                   \
        _Pragma("unroll")                                                      \
        for (int t = 0; t < 2; t++) {                                          \
            _Pragma("unroll")                                                  \
            for (int u = 0; u < 2; u++) {                                      \
                int idx = tid + u * 256;                                       \
                int r = idx >> 2, c = idx & 3;                                 \
                cp_async16(sb_ + t * TILEA + r * ROWB + c * 16,                \
                           srcA[t] + (size_t)r * K + k0_ + c * 8);             \
            }                                                                  \
        }                                                                      \
        _Pragma("unroll")                                                      \
        for (int t = 0; t < 2; t++) {                                          \
            uint32_t db_ = sb_ + 2 * TILEA + t * TILEBB;                       \
            _Pragma("unroll")                                                  \
            for (int u = 0; u < 4; u++) {                                      \
                int idx = tid + u * 256;                                       \
                int r = idx >> 2, c = idx & 3;                                 \
                cp_async16(db_ + r * ROWB + c * 16,                            \
                           srcB[t] + (size_t)r * K + k0_ + c * 8);             \
            }                                                                  \
        }                                                                      \
    } while (0)

    // prologue: stages 0,1 into buffers 0,1
    LOAD_STAGE(0, 0);
    cp_commit();
    LOAD_STAGE(1, 1);
    cp_commit();

    int buf = 0;        // buffer holding stage k
    int buf2 = 2;       // buffer for stage k+2
    for (int k = 0; k < NK; k++) {
        cp_wait<1>();
        __syncthreads();

        if (k + 2 < NK) LOAD_STAGE(k + 2, buf2);
        cp_commit();

        uint32_t sb = sbase + buf * STAGEB;
        uint32_t aAh = sb + offA, aAl = sb + TILEA + offA;
        uint32_t aBh = sb + 2 * TILEA + offB, aBl = sb + 2 * TILEA + TILEBB + offB;

#pragma unroll
        for (int ks = 0; ks < 2; ks++) {
            uint32_t ko = ks * 32;
            uint32_t ah[4][4], al[4][4];
#pragma unroll
            for (int mt = 0; mt < 4; mt++) {
                LDSM4(ah[mt], aAh + ko + mt * (16 * ROWB));
                LDSM4(al[mt], aAl + ko + mt * (16 * ROWB));
            }
#pragma unroll
            for (int p = 0; p < 4; p++) {
                uint32_t qh[4], ql[4];
                LDSM4(qh, aBh + ko + p * (16 * ROWB));
                LDSM4(ql, aBl + ko + p * (16 * ROWB));
#pragma unroll
                for (int mt = 0; mt < 4; mt++) {
                    MMA16816(acc[mt][2 * p], ah[mt], qh[0], qh[1]);
                    MMA16816(acc[mt][2 * p], ah[mt], ql[0], ql[1]);
                    MMA16816(acc[mt][2 * p], al[mt], qh[0], qh[1]);
                    MMA16816(acc[mt][2 * p + 1], ah[mt], qh[2], qh[3]);
                    MMA16816(acc[mt][2 * p + 1], ah[mt], ql[2], ql[3]);
                    MMA16816(acc[mt][2 * p + 1], al[mt], qh[2], qh[3]);
                }
            }
        }
        // rotate buffers: buf <- buf+1 (mod 3), buf2 <- buf2+1 (mod 3)
        buf = (buf == 2) ? 0 : buf + 1;
        buf2 = (buf2 == 2) ? 0 : buf2 + 1;
    }
#undef LOAD_STAGE

    // ---------------- epilogue (registers only) ----------------
    int l4 = lane >> 2, l2 = (lane & 3) * 2;
#pragma unroll
    for (int mt = 0; mt < 4; mt++) {
        int row = bm * 128 + mbase + mt * 16 + l4;
#pragma unroll
        for (int nt = 0; nt < 8; nt++) {
            int col = bn * 256 + nbase + nt * 8 + l2;
            float2 bv = *(const float2*)(bias + col);
            float v0 = acc[mt][nt][0] + bv.x;
            float v1 = acc[mt][nt][1] + bv.y;
            float v2 = acc[mt][nt][2] + bv.x;
            float v3 = acc[mt][nt][3] + bv.y;
            size_t p0 = (size_t)row * N + col;
            size_t p1 = (size_t)(row + 8) * N + col;
            if (EPI == 2) {
                float2 rv0 = *(const float2*)(res + p0);
                float2 rv1 = *(const float2*)(res + p1);
                v0 += rv0.x; v1 += rv0.y; v2 += rv1.x; v3 += rv1.y;
            }
            if (EPI == 1) {
                v0 = gelu_f(v0); v1 = gelu_f(v1);
                v2 = gelu_f(v2); v3 = gelu_f(v3);
                __nv_bfloat162 hp0, hp1, lp0, lp1;
                split_pair(v0, hp0.x, lp0.x);
                split_pair(v1, hp0.y, lp0.y);
                split_pair(v2, hp1.x, lp1.x);
                split_pair(v3, hp1.y, lp1.y);
                *(__nv_bfloat162*)(Oh + p0) = hp0;
                *(__nv_bfloat162*)(Oh + p1) = hp1;
                *(__nv_bfloat162*)(Ol + p0) = lp0;
                *(__nv_bfloat162*)(Ol + p1) = lp1;
            } else {
                *(float2*)(Cf + p0) = make_float2(v0, v1);
                *(float2*)(Cf + p1) = make_float2(v2, v3);
            }
        }
    }
}

// ---------------- Flash-style attention (fp32) -> bf16 pair output ---------
__global__ __launch_bounds__(256, 4) void attn_kernel(
    const float* __restrict__ qkv, const float* __restrict__ rel_bias,
    __nv_bfloat16* __restrict__ oh, __nv_bfloat16* __restrict__ ol) {
    __shared__ float Qt[64 * 64];
    __shared__ float KVs[64 * 64];
    __shared__ float Ps[64 * 64];
    int tid = threadIdx.x;
    int tx = tid & 15, ty = tid >> 4;
    int qt = blockIdx.x, h = blockIdx.y, b = blockIdx.z;

    const float* qbase = qkv + (size_t)(b * SEQ + qt * 64) * QKVD + h * HDIM;
    const float* kbase = qkv + (size_t)(b * SEQ) * QKVD + DM + h * HDIM;
    const float* vbase = kbase + DM;
    const float* biasrow = rel_bias + h * (2 * SEQ - 1);

    {
        int r = tid >> 2;
        int d0 = (tid & 3) << 4;
        const float* src = qbase + (size_t)r * QKVD + d0;
#pragma unroll
        for (int u = 0; u < 16; u += 4) {
            float4 v = *(const float4*)(src + u);
            Qt[(d0 + u + 0) * 64 + r] = v.x;
            Qt[(d0 + u + 1) * 64 + r] = v.y;
            Qt[(d0 + u + 2) * 64 + r] = v.z;
            Qt[(d0 + u + 3) * 64 + r] = v.w;
        }
    }

    float m[4], l[4], o[4][4];
#pragma unroll
    for (int i = 0; i < 4; i++) {
        m[i] = -1e30f;
        l[i] = 0.f;
#pragma unroll
        for (int c = 0; c < 4; c++) o[i][c] = 0.f;
    }

    for (int kt = 0; kt < 8; kt++) {
        __syncthreads();
        {
            int r = tid >> 2;
            int d0 = (tid & 3) << 4;
            const float* src = kbase + (size_t)(kt * 64 + r) * QKVD + d0;
#pragma unroll
            for (int u = 0; u < 16; u += 4) {
                float4 v = *(const float4*)(src + u);
                KVs[(d0 + u + 0) * 64 + r] = v.x;
                KVs[(d0 + u + 1) * 64 + r] = v.y;
                KVs[(d0 + u + 2) * 64 + r] = v.z;
                KVs[(d0 + u + 3) * 64 + r] = v.w;
            }
        }
        __syncthreads();

        float s[4][4];
#pragma unroll
        for (int i = 0; i < 4; i++)
#pragma unroll
            for (int j = 0; j < 4; j++) s[i][j] = 0.f;
#pragma unroll 16
        for (int d = 0; d < 64; d++) {
            float4 a = *(const float4*)&Qt[d * 64 + ty * 4];
            float4 bq = *(const float4*)&KVs[d * 64 + tx * 4];
            float aa[4] = {a.x, a.y, a.z, a.w};
            float bb[4] = {bq.x, bq.y, bq.z, bq.w};
#pragma unroll
            for (int i = 0; i < 4; i++)
#pragma unroll
                for (int j = 0; j < 4; j++) s[i][j] += aa[i] * bb[j];
        }

        int qg = qt * 64 + ty * 4;
        int kg = kt * 64 + tx * 4;
#pragma unroll
        for (int i = 0; i < 4; i++)
#pragma unroll
            for (int j = 0; j < 4; j++)
                s[i][j] = s[i][j] * 0.125f +
                          __ldg(&biasrow[(qg + i) - (kg + j) + (SEQ - 1)]);

        float mt[4];
#pragma unroll
        for (int i = 0; i < 4; i++) {
            mt[i] = fmaxf(fmaxf(s[i][0], s[i][1]), fmaxf(s[i][2], s[i][3]));
#pragma unroll
            for (int off = 8; off > 0; off >>= 1)
                mt[i] = fmaxf(mt[i], __shfl_xor_sync(0xffffffffu, mt[i], off, 16));
        }
        float fac[4];
#pragma unroll
        for (int i = 0; i < 4; i++) {
            float mn = fmaxf(m[i], mt[i]);
            fac[i] = __expf(m[i] - mn);
            m[i] = mn;
        }
        float rs[4];
#pragma unroll
        for (int i = 0; i < 4; i++) {
            rs[i] = 0.f;
#pragma unroll
            for (int j = 0; j < 4; j++) {
                float p = __expf(s[i][j] - m[i]);
                s[i][j] = p;
                rs[i] += p;
            }
#pragma unroll
            for (int off = 8; off > 0; off >>= 1)
                rs[i] += __shfl_xor_sync(0xffffffffu, rs[i], off, 16);
            l[i] = l[i] * fac[i] + rs[i];
#pragma unroll
            for (int c = 0; c < 4; c++) o[i][c] *= fac[i];
        }
#pragma unroll
        for (int i = 0; i < 4; i++)
            *(float4*)&Ps[(ty * 4 + i) * 64 + tx * 4] =
                make_float4(s[i][0], s[i][1], s[i][2], s[i][3]);
        __syncthreads();

        {
            int r = tid >> 2;
            int d0 = (tid & 3) << 4;
            const float* src = vbase + (size_t)(kt * 64 + r) * QKVD + d0;
#pragma unroll
            for (int u = 0; u < 16; u += 4)
                *(float4*)&KVs[r * 64 + d0 + u] = *(const float4*)(src + u);
        }
        __syncthreads();

#pragma unroll 16
        for (int j = 0; j < 64; j++) {
            float pa[4];
#pragma unroll
            for (int i = 0; i < 4; i++) pa[i] = Ps[(ty * 4 + i) * 64 + j];
            float4 vb = *(const float4*)&KVs[j * 64 + tx * 4];
            float vv[4] = {vb.x, vb.y, vb.z, vb.w};
#pragma unroll
            for (int i = 0; i < 4; i++)
#pragma unroll
                for (int c = 0; c < 4; c++) o[i][c] += pa[i] * vv[c];
        }
    }

    size_t obase = (size_t)(b * SEQ + qt * 64) * DM + h * HDIM;
#pragma unroll
    for (int i = 0; i < 4; i++) {
        float inv = 1.f / l[i];
        float v0 = o[i][0] * inv, v1 = o[i][1] * inv;
        float v2 = o[i][2] * inv, v3 = o[i][3] * inv;
        __nv_bfloat162 hp0, hp1, lp0, lp1;
        split_pair(v0, hp0.x, lp0.x);
        split_pair(v1, hp0.y, lp0.y);
        split_pair(v2, hp1.x, lp1.x);
        split_pair(v3, hp1.y, lp1.y);
        size_t p = obase + (size_t)(ty * 4 + i) * DM + tx * 4;
        *(__nv_bfloat162*)(oh + p) = hp0;
        *(__nv_bfloat162*)(oh + p + 2) = hp1;
        *(__nv_bfloat162*)(ol + p) = lp0;
        *(__nv_bfloat162*)(ol + p + 2) = lp1;
    }
}

// ---------------- launch ---------------------------------------------------
extern "C" void kernel_launch(void* const* d_in, const int* in_sizes, int n_in,
                              void* d_out, int out_size) {
    const float* x = (const float*)d_in[0];
    const float* in_w = (const float*)d_in[1];
    const float* in_b = (const float*)d_in[2];
    const float* out_w = (const float*)d_in[3];
    const float* out_b = (const float*)d_in[4];
    const float* rel_bias = (const float*)d_in[5];
    const float* w1 = (const float*)d_in[6];
    const float* b1 = (const float*)d_in[7];
    const float* w2 = (const float*)d_in[8];
    const float* b2 = (const float*)d_in[9];
    const float* ln1w = (const float*)d_in[10];
    const float* ln1b = (const float*)d_in[11];
    const float* ln2w = (const float*)d_in[12];
    const float* ln2b = (const float*)d_in[13];
    float* out = (float*)d_out;

    __nv_bfloat16 *wh, *wl, *xh, *xl, *ah, *al;
    float* qkv;
    cudaGetSymbolAddress((void**)&wh, g_wh);
    cudaGetSymbolAddress((void**)&wl, g_wl);
    cudaGetSymbolAddress((void**)&xh, g_xh);
    cudaGetSymbolAddress((void**)&xl, g_xl);
    cudaGetSymbolAddress((void**)&ah, g_ah);
    cudaGetSymbolAddress((void**)&al, g_al);
    cudaGetSymbolAddress((void**)&qkv, g_qkv);

    cudaFuncSetAttribute(gemm_bf16x3<0>, cudaFuncAttributeMaxDynamicSharedMemorySize, SMEM_BYTES);
    cudaFuncSetAttribute(gemm_bf16x3<1>, cudaFuncAttributeMaxDynamicSharedMemorySize, SMEM_BYTES);
    cudaFuncSetAttribute(gemm_bf16x3<2>, cudaFuncAttributeMaxDynamicSharedMemorySize, SMEM_BYTES);

    const size_t OFF_INW = 0;
    const size_t OFF_OUTW = 3145728;
    const size_t OFF_W1 = 4194304;
    const size_t OFF_W2 = 8388608;

    cvt_pair<<<(3145728 / 4 + 255) / 256, 256>>>(in_w, wh + OFF_INW, wl + OFF_INW, 3145728 / 4);
    cvt_pair<<<(1048576 / 4 + 255) / 256, 256>>>(out_w, wh + OFF_OUTW, wl + OFF_OUTW, 1048576 / 4);
    cvt_pair<<<(4194304 / 4 + 255) / 256, 256>>>(w1, wh + OFF_W1, wl + OFF_W1, 4194304 / 4);
    cvt_pair<<<(4194304 / 4 + 255) / 256, 256>>>(w2, wh + OFF_W2, wl + OFF_W2, 4194304 / 4);

    // 1. xn = LN1(x) -> bf16 pair
    ln_pair_kernel<<<MROWS, 256>>>(x, ln1w, ln1b, xh, xl);
    // 2. qkv = xn @ in_proj_w^T + b
    gemm_bf16x3<0><<<dim3(QKVD / 256, MROWS / 128), 256, SMEM_BYTES>>>(
        xh, xl, wh + OFF_INW, wl + OFF_INW, in_b, nullptr, qkv, nullptr, nullptr,
        QKVD, DM);
    // 3. attention -> bf16 pair (fused)
    attn_kernel<<<dim3(SEQ / 64, NH, BSZ), 256>>>(qkv, rel_bias, xh, xl);
    // 4. out = x + attn @ out_w^T + b
    gemm_bf16x3<2><<<dim3(DM / 256, MROWS / 128), 256, SMEM_BYTES>>>(
        xh, xl, wh + OFF_OUTW, wl + OFF_OUTW, out_b, x, out, nullptr, nullptr,
        DM, DM);
    // 5. xn = LN2(out) -> bf16 pair
    ln_pair_kernel<<<MROWS, 256>>>(out, ln2w, ln2b, xh, xl);
    // 6. ffn = gelu(xn @ w1^T + b1) -> bf16 pair
    gemm_bf16x3<1><<<dim3(DFF / 256, MROWS / 128), 256, SMEM_BYTES>>>(
        xh, xl, wh + OFF_W1, wl + OFF_W1, b1, nullptr, nullptr, ah, al,
        DFF, DM);
    // 7. out = out + ffn @ w2^T + b2
    gemm_bf16x3<2><<<dim3(DM / 256, MROWS / 128), 256, SMEM_BYTES>>>(
        ah, al, wh + OFF_W2, wl + OFF_W2, b2, out, out, nullptr, nullptr,
        DM, DFF);
}